// round 1
// baseline (speedup 1.0000x reference)
#include <cuda_runtime.h>
#include <math.h>

#define BATCH 4
#define NTOK  4096      // N = 64*64
#define CDIM  256
#define NH    8
#define HD    32
#define RESHW 64
#define PLP   64        // pooled length (8*8)
#define TBLN  4096
#define EPSF  1.1920929e-07f

// ---------------- scratch (device globals; no dynamic alloc) ----------------
__device__ float g_q   [BATCH*NTOK*CDIM];    // raw q, then q_norm (overwritten)
__device__ float g_qs  [BATCH*NTOK*CDIM];    // q_scaled
__device__ float g_kv  [BATCH*NTOK*2*CDIM];  // kv; k half L2-normalized in place
__device__ float g_sr  [BATCH*NTOK*CDIM];    // gelu(conv1x1(x))
__device__ float g_att [BATCH*NTOK*CDIM];    // attention out (pre-proj)
__device__ float g_gate[BATCH*NTOK*NH];      // masked head gates
__device__ float g_pool[BATCH*PLP*CDIM];     // pooled + LN
__device__ float g_kvp [BATCH*PLP*2*CDIM];   // pooled kv; k half normalized
__device__ float g_cpb [TBLN*NH];            // cpb table (row, head)

__device__ __forceinline__ float warp_sum(float v) {
#pragma unroll
    for (int o = 16; o; o >>= 1) v += __shfl_xor_sync(0xffffffffu, v, o);
    return v;
}
__device__ __forceinline__ float warp_max(float v) {
#pragma unroll
    for (int o = 16; o; o >>= 1) v = fmaxf(v, __shfl_xor_sync(0xffffffffu, v, o));
    return v;
}

// ---------------- SGEMM: C[M,N] = A[M,K] @ W[N,K]^T + bias, opt. exact GELU ----
// BM=BN=64, BK=16, 256 threads, 4x4 micro-tile. M%64==0, N%64==0, K%16==0.
template<int ACT>
__global__ void __launch_bounds__(256)
sgemm_nt(const float* __restrict__ A, const float* __restrict__ W,
         const float* __restrict__ bias, float* __restrict__ C,
         int M, int N, int K) {
    __shared__ float As[16][68];
    __shared__ float Bs[16][68];
    const int bm = blockIdx.y * 64, bn = blockIdx.x * 64;
    const int tid  = threadIdx.x;
    const int lrow = tid >> 2;           // 0..63
    const int lk   = (tid & 3) << 2;     // 0,4,8,12
    const int ty   = tid >> 4;           // 0..15 (m-subtile)
    const int tx   = tid & 15;           // 0..15 (n-subtile)
    float acc[4][4] = {};
    const float* Aptr = A + (size_t)(bm + lrow) * K + lk;
    const float* Wptr = W + (size_t)(bn + lrow) * K + lk;
    for (int k0 = 0; k0 < K; k0 += 16) {
        float4 av = *(const float4*)(Aptr + k0);
        float4 wv = *(const float4*)(Wptr + k0);
        As[lk + 0][lrow] = av.x; As[lk + 1][lrow] = av.y;
        As[lk + 2][lrow] = av.z; As[lk + 3][lrow] = av.w;
        Bs[lk + 0][lrow] = wv.x; Bs[lk + 1][lrow] = wv.y;
        Bs[lk + 2][lrow] = wv.z; Bs[lk + 3][lrow] = wv.w;
        __syncthreads();
#pragma unroll
        for (int k = 0; k < 16; k++) {
            float a[4], bv[4];
#pragma unroll
            for (int i = 0; i < 4; i++) a[i]  = As[k][ty * 4 + i];
#pragma unroll
            for (int j = 0; j < 4; j++) bv[j] = Bs[k][tx * 4 + j];
#pragma unroll
            for (int i = 0; i < 4; i++)
#pragma unroll
                for (int j = 0; j < 4; j++)
                    acc[i][j] += a[i] * bv[j];
        }
        __syncthreads();
    }
#pragma unroll
    for (int i = 0; i < 4; i++) {
        int m = bm + ty * 4 + i;
#pragma unroll
        for (int j = 0; j < 4; j++) {
            int nn = bn + tx * 4 + j;
            float v = acc[i][j] + bias[nn];
            if (ACT == 1) v = 0.5f * v * (1.0f + erff(v * 0.70710678118654752f));
            C[(size_t)m * N + nn] = v;
        }
    }
}

// ---------------- gating: one warp per token -------------------------------
__global__ void __launch_bounds__(256)
gating_kernel(const float* __restrict__ x, const float* __restrict__ wg,
              const float* __restrict__ wg0, const float* __restrict__ wg1) {
    int t = blockIdx.x * 8 + (threadIdx.x >> 5);
    int lane = threadIdx.x & 31;
    const float* xt = x + (size_t)t * CDIM;
    float xv[8];
#pragma unroll
    for (int j = 0; j < 8; j++) xv[j] = xt[lane + 32 * j];
    float d[10];
#pragma unroll
    for (int i = 0; i < 10; i++) {
        const float* wr = (i < 4) ? wg + i * CDIM
                        : (i < 8) ? wg1 + (i - 4) * CDIM
                                  : wg0 + (i - 8) * CDIM;
        float s = 0.f;
#pragma unroll
        for (int j = 0; j < 8; j++) s += xv[j] * wr[lane + 32 * j];
        d[i] = warp_sum(s);
    }
    // routed gates (top-2 of softmax over d[0..3], renorm, *2)
    float m0 = fmaxf(fmaxf(d[0], d[1]), fmaxf(d[2], d[3]));
    float e[4], se = 0.f;
#pragma unroll
    for (int i = 0; i < 4; i++) { e[i] = expf(d[i] - m0); se += e[i]; }
    float gsm[4];
#pragma unroll
    for (int i = 0; i < 4; i++) gsm[i] = e[i] / se;
    int i1 = 0;
#pragma unroll
    for (int i = 1; i < 4; i++) if (gsm[i] > gsm[i1]) i1 = i;
    int i2 = -1;
#pragma unroll
    for (int i = 0; i < 4; i++) {
        if (i == i1) continue;
        if (i2 < 0 || gsm[i] > gsm[i2]) i2 = i;
    }
    float rs = fmaxf(gsm[i1] + gsm[i2], EPSF);
    float routed[4];
#pragma unroll
    for (int i = 0; i < 4; i++)
        routed[i] = (i == i1 || i == i2) ? gsm[i] / rs * 2.f : 0.f;
    // shared gates: softmax over d[4..7] * 4
    float m1 = fmaxf(fmaxf(d[4], d[5]), fmaxf(d[6], d[7]));
    float es[4], ss = 0.f;
#pragma unroll
    for (int i = 0; i < 4; i++) { es[i] = expf(d[4 + i] - m1); ss += es[i]; }
    float shg[4];
#pragma unroll
    for (int i = 0; i < 4; i++) shg[i] = es[i] / ss * 4.f;
    // w0: softmax over d[8..9] * 2
    float m2 = fmaxf(d[8], d[9]);
    float e8 = expf(d[8] - m2), e9 = expf(d[9] - m2);
    float w00 = e8 / (e8 + e9) * 2.f;
    float w01 = e9 / (e8 + e9) * 2.f;
    if (lane < NH) {
        float v = (lane < 4) ? w00 * shg[lane] : w01 * routed[lane - 4];
        g_gate[(size_t)t * NH + lane] = v;
    }
}

// ---------------- q postprocess: normalize + embed + temp + sls -------------
__global__ void __launch_bounds__(256)
q_post(const float* __restrict__ temp, const float* __restrict__ qe) {
    int bn = blockIdx.x;                       // 0..B*N-1
    int h = threadIdx.x >> 5, lane = threadIdx.x & 31;
    int n = bn & (NTOK - 1);
    size_t off = (size_t)bn * CDIM + h * HD + lane;
    float v = g_q[off];
    float nrm = sqrtf(warp_sum(v * v));
    float qn = v / fmaxf(nrm, EPSF);
    int y = n >> 6, x = n & 63;
    int ch = min(y + 1, 63) - max(y - 1, 0) + 1;
    int cw = min(x + 1, 63) - max(x - 1, 0) + 1;
    float sls = logf((float)(ch * cw + PLP));
    float sp = log1pf(expf(temp[h]));
    g_q [off] = qn;
    g_qs[off] = (qn + qe[h * HD + lane]) * sp * sls;
}

// ---------------- normalize k half of kv (in place) -------------------------
__global__ void __launch_bounds__(256) kv_post() {
    int bn = blockIdx.x;
    int h = threadIdx.x >> 5, lane = threadIdx.x & 31;
    size_t off = (size_t)bn * 2 * CDIM + h * HD + lane;
    float v = g_kv[off];
    float nrm = sqrtf(warp_sum(v * v));
    g_kv[off] = v / fmaxf(nrm, EPSF);
}

__global__ void __launch_bounds__(256) kvpool_post() {
    int bp = blockIdx.x;                        // 0..B*PL-1
    int h = threadIdx.x >> 5, lane = threadIdx.x & 31;
    size_t off = (size_t)bp * 2 * CDIM + h * HD + lane;
    float v = g_kvp[off];
    float nrm = sqrtf(warp_sum(v * v));
    g_kvp[off] = v / fmaxf(nrm, EPSF);
}

// ---------------- 8x8 avg pool + LayerNorm ----------------------------------
__global__ void __launch_bounds__(256)
pool_ln(const float* __restrict__ gw, const float* __restrict__ gb) {
    int bp = blockIdx.x;                 // b*64 + p
    int b = bp >> 6, p = bp & 63;
    int py = p >> 3, px = p & 7;
    int c = threadIdx.x;
    const float* base = g_sr + (size_t)b * NTOK * CDIM;
    float s = 0.f;
    for (int iy = 0; iy < 8; iy++) {
        int y = py * 8 + iy;
        for (int ix = 0; ix < 8; ix++) {
            int n = y * RESHW + px * 8 + ix;
            s += base[(size_t)n * CDIM + c];
        }
    }
    float val = s * (1.0f / 64.0f);
    __shared__ float red[256];
    red[c] = val; __syncthreads();
    for (int st = 128; st > 0; st >>= 1) { if (c < st) red[c] += red[c + st]; __syncthreads(); }
    float mu = red[0] * (1.0f / 256.0f);
    __syncthreads();
    float dv = val - mu;
    red[c] = dv * dv; __syncthreads();
    for (int st = 128; st > 0; st >>= 1) { if (c < st) red[c] += red[c + st]; __syncthreads(); }
    float var = red[0] * (1.0f / 256.0f);
    g_pool[(size_t)bp * CDIM + c] = dv * rsqrtf(var + 1e-5f) * gw[c] + gb[c];
}

// ---------------- cpb MLP: (2 -> 512 relu -> 8) per table row ---------------
__global__ void __launch_bounds__(128)
cpb_kernel(const float* __restrict__ tbl, const float* __restrict__ w1,
           const float* __restrict__ b1, const float* __restrict__ w2,
           const float* __restrict__ b2) {
    int row = blockIdx.x;
    int tid = threadIdx.x;
    float t0 = tbl[row * 2 + 0], t1 = tbl[row * 2 + 1];
    float acc[8] = {};
    for (int j = tid; j < 512; j += 128) {
        float hv = fmaxf(t0 * w1[2 * j] + t1 * w1[2 * j + 1] + b1[j], 0.f);
#pragma unroll
        for (int o = 0; o < 8; o++) acc[o] += hv * w2[o * 512 + j];
    }
#pragma unroll
    for (int o = 0; o < 8; o++) acc[o] = warp_sum(acc[o]);
    __shared__ float sh[4][8];
    int wp = tid >> 5, lane = tid & 31;
    if (lane == 0)
#pragma unroll
        for (int o = 0; o < 8; o++) sh[wp][o] = acc[o];
    __syncthreads();
    if (tid < 8)
        g_cpb[(size_t)row * 8 + tid] =
            sh[0][tid] + sh[1][tid] + sh[2][tid] + sh[3][tid] + b2[tid];
}

// ---------------- fused attention core --------------------------------------
// block = (b, h, 8 consecutive tokens); warp per token; lane = head dim.
__global__ void __launch_bounds__(256)
attn_kernel(const float* __restrict__ rpb, const float* __restrict__ lt,
            const float* __restrict__ lb, const int* __restrict__ rel_idx) {
    int blk = blockIdx.x;
    int ntile = blk & 511;
    int h = (blk >> 9) & 7;
    int b = blk >> 12;
    int w = threadIdx.x >> 5, lane = threadIdx.x & 31;
    __shared__ float kp[64][33];
    __shared__ float vp[64][33];
    __shared__ float logit[8][80];
    __shared__ float qsh[8][32];
    for (int i = threadIdx.x; i < 64 * 32; i += 256) {
        int p = i >> 5, d = i & 31;
        size_t base = (size_t)(b * PLP + p) * 2 * CDIM + h * HD + d;
        kp[p][d] = g_kvp[base];
        vp[p][d] = g_kvp[base + CDIM];
    }
    __syncthreads();
    int n = ntile * 8 + w;
    int y = n >> 6, x = n & 63;
    size_t qoff = (size_t)(b * NTOK + n) * CDIM + h * HD + lane;
    float qsv = g_qs[qoff];
    float qnv = g_q[qoff];
    qsh[w][lane] = qsv;
    // 9 local logits (zero-padded window)
#pragma unroll
    for (int l = 0; l < 9; l++) {
        int yy = y + l / 3 - 1, xx = x + l % 3 - 1;
        float dot = 0.f;
        if ((unsigned)yy < 64u && (unsigned)xx < 64u) {
            int n2 = yy * RESHW + xx;
            dot = warp_sum(qsv * g_kv[(size_t)(b * NTOK + n2) * 2 * CDIM + h * HD + lane]);
        }
        if (lane == 0) logit[w][l] = dot + rpb[h * 9 + l];
    }
    __syncwarp();
    // 64 pool logits: lane-serial dots (p = lane, lane+32)
    const int* ridx = rel_idx + (size_t)n * PLP;
#pragma unroll
    for (int rr = 0; rr < 2; rr++) {
        int p = lane + rr * 32;
        float dot = 0.f;
#pragma unroll
        for (int j = 0; j < 32; j++) dot += qsh[w][j] * kp[p][j];
        logit[w][9 + p] = dot + g_cpb[(size_t)ridx[p] * 8 + h];
    }
    __syncwarp();
    // softmax over 73
    float v0 = logit[w][lane];
    float v1 = logit[w][lane + 32];
    float v2 = (lane < 9) ? logit[w][lane + 64] : -3.4e38f;
    float mx = warp_max(fmaxf(fmaxf(v0, v1), v2));
    float e0 = expf(v0 - mx), e1 = expf(v1 - mx);
    float e2 = (lane < 9) ? expf(v2 - mx) : 0.f;
    float inv = 1.0f / warp_sum(e0 + e1 + e2);
    logit[w][lane] = e0 * inv;
    logit[w][lane + 32] = e1 * inv;
    if (lane < 9) logit[w][lane + 64] = e2 * inv;
    __syncwarp();
    // a_loc += q_norm . learnable_tokens + learnable_bias
#pragma unroll
    for (int l = 0; l < 9; l++) {
        float d2 = warp_sum(qnv * lt[h * (HD * 9) + lane * 9 + l]);
        if (lane == 0) logit[w][l] += d2 + lb[h * 9 + l];
    }
    __syncwarp();
    // output accumulation (lane = d)
    float outv = 0.f;
#pragma unroll
    for (int l = 0; l < 9; l++) {
        int yy = y + l / 3 - 1, xx = x + l % 3 - 1;
        if ((unsigned)yy < 64u && (unsigned)xx < 64u) {
            int n2 = yy * RESHW + xx;
            outv += logit[w][l] *
                    g_kv[(size_t)(b * NTOK + n2) * 2 * CDIM + CDIM + h * HD + lane];
        }
    }
#pragma unroll 8
    for (int p = 0; p < 64; p++) outv += logit[w][9 + p] * vp[p][lane];
    float gt = g_gate[(size_t)(b * NTOK + n) * NH + h];
    g_att[(size_t)(b * NTOK + n) * CDIM + h * HD + lane] = outv * gt;
}

// ---------------- launch ----------------------------------------------------
extern "C" void kernel_launch(void* const* d_in, const int* in_sizes, int n_in,
                              void* d_out, int out_size) {
    const float* x      = (const float*)d_in[0];
    const float* rct    = (const float*)d_in[1];
    const float* q_w    = (const float*)d_in[2];
    const float* q_b    = (const float*)d_in[3];
    const float* kv_w   = (const float*)d_in[4];
    const float* kv_b   = (const float*)d_in[5];
    const float* temp   = (const float*)d_in[6];
    const float* qe     = (const float*)d_in[7];
    const float* rpb    = (const float*)d_in[8];
    const float* lt     = (const float*)d_in[9];
    const float* lb     = (const float*)d_in[10];
    const float* cpb1_w = (const float*)d_in[11];
    const float* cpb1_b = (const float*)d_in[12];
    const float* cpb2_w = (const float*)d_in[13];
    const float* cpb2_b = (const float*)d_in[14];
    const float* sr_w   = (const float*)d_in[15];
    const float* sr_b   = (const float*)d_in[16];
    const float* norm_g = (const float*)d_in[17];
    const float* norm_b = (const float*)d_in[18];
    const float* wg_w   = (const float*)d_in[19];
    const float* wg0_w  = (const float*)d_in[20];
    const float* wg1_w  = (const float*)d_in[21];
    const float* proj_w = (const float*)d_in[22];
    const float* proj_b = (const float*)d_in[23];
    const int*   ridx   = (const int*)d_in[24];
    float* out = (float*)d_out;

    float *pq, *pkv, *psr, *patt, *ppool, *pkvp;
    cudaGetSymbolAddress((void**)&pq,    g_q);
    cudaGetSymbolAddress((void**)&pkv,   g_kv);
    cudaGetSymbolAddress((void**)&psr,   g_sr);
    cudaGetSymbolAddress((void**)&patt,  g_att);
    cudaGetSymbolAddress((void**)&ppool, g_pool);
    cudaGetSymbolAddress((void**)&pkvp,  g_kvp);

    const int M = BATCH * NTOK;                 // 16384
    dim3 gq(CDIM / 64, M / 64);                 // 4 x 256
    dim3 gkv(2 * CDIM / 64, M / 64);            // 8 x 256
    dim3 gkvp(2 * CDIM / 64, (BATCH * PLP) / 64); // 8 x 4

    sgemm_nt<0><<<gq, 256>>>(x, q_w, q_b, pq, M, CDIM, CDIM);
    sgemm_nt<0><<<gkv, 256>>>(x, kv_w, kv_b, pkv, M, 2 * CDIM, CDIM);
    sgemm_nt<1><<<gq, 256>>>(x, sr_w, sr_b, psr, M, CDIM, CDIM);
    gating_kernel<<<M / 8, 256>>>(x, wg_w, wg0_w, wg1_w);
    q_post<<<M, 256>>>(temp, qe);
    kv_post<<<M, 256>>>();
    pool_ln<<<BATCH * PLP, 256>>>(norm_g, norm_b);
    sgemm_nt<0><<<gkvp, 256>>>(ppool, kv_w, kv_b, pkvp, BATCH * PLP, 2 * CDIM, CDIM);
    kvpool_post<<<BATCH * PLP, 256>>>();
    cpb_kernel<<<TBLN, 128>>>(rct, cpb1_w, cpb1_b, cpb2_w, cpb2_b);
    attn_kernel<<<BATCH * NH * (NTOK / 8), 256>>>(rpb, lt, lb, ridx);
    sgemm_nt<0><<<gq, 256>>>(patt, proj_w, proj_b, out, M, CDIM, CDIM);
}

// round 3
// speedup vs baseline: 1.3419x; 1.3419x over previous
#include <cuda_runtime.h>
#include <cuda_bf16.h>
#include <math.h>
#include <stdint.h>

#define BATCH 4
#define NTOK  4096      // N = 64*64
#define CDIM  256
#define NH    8
#define HD    32
#define RESHW 64
#define PLP   64        // pooled length (8*8)
#define TBLN  4096
#define EPSF  1.1920929e-07f

// ---------------- scratch (device globals; no dynamic alloc) ----------------
__device__ float g_q   [BATCH*NTOK*CDIM];    // raw q, then q_norm (overwritten)
__device__ float g_qs  [BATCH*NTOK*CDIM];    // q_scaled
__device__ float g_kv  [BATCH*NTOK*2*CDIM];  // kv; k half L2-normalized in place
__device__ float g_sr  [BATCH*NTOK*CDIM];    // gelu(conv1x1(x))
__device__ float g_att [BATCH*NTOK*CDIM];    // attention out (pre-proj)
__device__ float g_gate[BATCH*NTOK*NH];      // masked head gates
__device__ float g_pool[BATCH*PLP*CDIM];     // pooled + LN
__device__ float g_kvp [BATCH*PLP*2*CDIM];   // pooled kv; k half normalized
__device__ float g_cpb [TBLN*NH];            // cpb table (row, head)

__device__ __forceinline__ float warp_sum(float v) {
#pragma unroll
    for (int o = 16; o; o >>= 1) v += __shfl_xor_sync(0xffffffffu, v, o);
    return v;
}
__device__ __forceinline__ float warp_max(float v) {
#pragma unroll
    for (int o = 16; o; o >>= 1) v = fmaxf(v, __shfl_xor_sync(0xffffffffu, v, o));
    return v;
}

// ================= mma.sync bf16 helpers (compute_103-safe) =================
__device__ __forceinline__ uint32_t smem_u32(const void* p) {
    uint32_t a;
    asm("{ .reg .u64 t; cvta.to.shared.u64 t, %1; cvt.u32.u64 %0, t; }"
        : "=r"(a) : "l"(p));
    return a;
}
__device__ __forceinline__ void ldsm_x4(uint32_t* r, uint32_t addr) {
    asm volatile("ldmatrix.sync.aligned.m8n8.x4.shared.b16 {%0,%1,%2,%3}, [%4];"
                 : "=r"(r[0]), "=r"(r[1]), "=r"(r[2]), "=r"(r[3]) : "r"(addr));
}
__device__ __forceinline__ void ldsm_x2(uint32_t* r, uint32_t addr) {
    asm volatile("ldmatrix.sync.aligned.m8n8.x2.shared.b16 {%0,%1}, [%2];"
                 : "=r"(r[0]), "=r"(r[1]) : "r"(addr));
}
__device__ __forceinline__ void mma_bf16(float* c, const uint32_t* a,
                                         const uint32_t* b) {
    asm volatile(
        "mma.sync.aligned.m16n8k16.row.col.f32.bf16.bf16.f32 "
        "{%0,%1,%2,%3}, {%4,%5,%6,%7}, {%8,%9}, {%0,%1,%2,%3};"
        : "+f"(c[0]), "+f"(c[1]), "+f"(c[2]), "+f"(c[3])
        : "r"(a[0]), "r"(a[1]), "r"(a[2]), "r"(a[3]), "r"(b[0]), "r"(b[1]));
}
// pack two floats as bf16x2 (elem k in low half, k+1 in high half)
__device__ __forceinline__ uint32_t pack_bf16(float e0, float e1) {
    uint32_t r;
    asm("cvt.rn.bf16x2.f32 %0, %1, %2;" : "=r"(r) : "f"(e1), "f"(e0));
    return r;
}
__device__ __forceinline__ float bf16_round(float a) {
    return __bfloat162float(__float2bfloat16_rn(a));
}

// ================= 3-term bf16 GEMM on tensor cores =========================
// C[M,N] = A[M,256] @ W[N,256]^T + bias, optional exact GELU.
// CTA tile 128x128, 8 warps (4 m x 2 n), warp tile 32x64, K-chunk 32.
#define SMSTRIDE 40
template<int ACT>
__global__ void __launch_bounds__(256)
gemm_bf16x3(const float* __restrict__ A, const float* __restrict__ W,
            const float* __restrict__ bias, float* __restrict__ C,
            int M, int N) {
    __shared__ __align__(16) uint16_t sAh[128][SMSTRIDE];
    __shared__ __align__(16) uint16_t sAl[128][SMSTRIDE];
    __shared__ __align__(16) uint16_t sBh[128][SMSTRIDE];
    __shared__ __align__(16) uint16_t sBl[128][SMSTRIDE];
    const int bm = blockIdx.y * 128, bn = blockIdx.x * 128;
    const int tid = threadIdx.x, lane = tid & 31, wid = tid >> 5;
    const int wm = (wid & 3) * 32, wn = (wid >> 2) * 64;
    float acc[2][8][4] = {};

    for (int kc = 0; kc < 8; kc++) {
        const int k0 = kc * 32;
#pragma unroll
        for (int t = 0; t < 4; t++) {
            int f = tid + t * 256;
            int row = f >> 3, kq = (f & 7) << 2;
            float4 a = *(const float4*)(A + (size_t)(bm + row) * 256 + k0 + kq);
            float4 b = *(const float4*)(W + (size_t)(bn + row) * 256 + k0 + kq);
            float ah0 = bf16_round(a.x), ah1 = bf16_round(a.y);
            float ah2 = bf16_round(a.z), ah3 = bf16_round(a.w);
            float bh0 = bf16_round(b.x), bh1 = bf16_round(b.y);
            float bh2 = bf16_round(b.z), bh3 = bf16_round(b.w);
            uint32_t* pAh = (uint32_t*)&sAh[row][kq];
            uint32_t* pAl = (uint32_t*)&sAl[row][kq];
            uint32_t* pBh = (uint32_t*)&sBh[row][kq];
            uint32_t* pBl = (uint32_t*)&sBl[row][kq];
            pAh[0] = pack_bf16(ah0, ah1);
            pAh[1] = pack_bf16(ah2, ah3);
            pAl[0] = pack_bf16(a.x - ah0, a.y - ah1);
            pAl[1] = pack_bf16(a.z - ah2, a.w - ah3);
            pBh[0] = pack_bf16(bh0, bh1);
            pBh[1] = pack_bf16(bh2, bh3);
            pBl[0] = pack_bf16(b.x - bh0, b.y - bh1);
            pBl[1] = pack_bf16(b.z - bh2, b.w - bh3);
        }
        __syncthreads();
#pragma unroll
        for (int ks = 0; ks < 2; ks++) {
            uint32_t ah[2][4], al[2][4];
            const int arow = lane & 15, acol = ks * 16 + (lane >> 4) * 8;
#pragma unroll
            for (int i = 0; i < 2; i++) {
                ldsm_x4(ah[i], smem_u32(&sAh[wm + i * 16 + arow][acol]));
                ldsm_x4(al[i], smem_u32(&sAl[wm + i * 16 + arow][acol]));
            }
            const int brow0 = wn + (lane & 7);
            const int bcol = ks * 16 + ((lane >> 3) & 1) * 8;
#pragma unroll
            for (int j = 0; j < 8; j++) {
                uint32_t bh[2], bl[2];
                ldsm_x2(bh, smem_u32(&sBh[brow0 + j * 8][bcol]));
                ldsm_x2(bl, smem_u32(&sBl[brow0 + j * 8][bcol]));
#pragma unroll
                for (int i = 0; i < 2; i++) {
                    mma_bf16(acc[i][j], ah[i], bh);
                    mma_bf16(acc[i][j], ah[i], bl);
                    mma_bf16(acc[i][j], al[i], bh);
                }
            }
        }
        __syncthreads();
    }
    // epilogue: registers -> gmem (fragment layout), bias + optional GELU
#pragma unroll
    for (int i = 0; i < 2; i++) {
        int r0 = bm + wm + i * 16 + (lane >> 2);
#pragma unroll
        for (int j = 0; j < 8; j++) {
            int col = bn + wn + j * 8 + (lane & 3) * 2;
            float b0 = bias[col], b1 = bias[col + 1];
            float v0 = acc[i][j][0] + b0, v1 = acc[i][j][1] + b1;
            float v2 = acc[i][j][2] + b0, v3 = acc[i][j][3] + b1;
            if (ACT == 1) {
                v0 = 0.5f * v0 * (1.0f + erff(v0 * 0.70710678118654752f));
                v1 = 0.5f * v1 * (1.0f + erff(v1 * 0.70710678118654752f));
                v2 = 0.5f * v2 * (1.0f + erff(v2 * 0.70710678118654752f));
                v3 = 0.5f * v3 * (1.0f + erff(v3 * 0.70710678118654752f));
            }
            float2 o01; o01.x = v0; o01.y = v1;
            float2 o23; o23.x = v2; o23.y = v3;
            *(float2*)(C + (size_t)r0 * N + col) = o01;
            *(float2*)(C + (size_t)(r0 + 8) * N + col) = o23;
        }
    }
}

// ---------------- gating: one warp per token -------------------------------
__global__ void __launch_bounds__(256)
gating_kernel(const float* __restrict__ x, const float* __restrict__ wg,
              const float* __restrict__ wg0, const float* __restrict__ wg1) {
    int t = blockIdx.x * 8 + (threadIdx.x >> 5);
    int lane = threadIdx.x & 31;
    const float* xt = x + (size_t)t * CDIM;
    float xv[8];
#pragma unroll
    for (int j = 0; j < 8; j++) xv[j] = xt[lane + 32 * j];
    float d[10];
#pragma unroll
    for (int i = 0; i < 10; i++) {
        const float* wr = (i < 4) ? wg + i * CDIM
                        : (i < 8) ? wg1 + (i - 4) * CDIM
                                  : wg0 + (i - 8) * CDIM;
        float s = 0.f;
#pragma unroll
        for (int j = 0; j < 8; j++) s += xv[j] * wr[lane + 32 * j];
        d[i] = warp_sum(s);
    }
    float m0 = fmaxf(fmaxf(d[0], d[1]), fmaxf(d[2], d[3]));
    float e[4], se = 0.f;
#pragma unroll
    for (int i = 0; i < 4; i++) { e[i] = expf(d[i] - m0); se += e[i]; }
    float gsm[4];
#pragma unroll
    for (int i = 0; i < 4; i++) gsm[i] = e[i] / se;
    int i1 = 0;
#pragma unroll
    for (int i = 1; i < 4; i++) if (gsm[i] > gsm[i1]) i1 = i;
    int i2 = -1;
#pragma unroll
    for (int i = 0; i < 4; i++) {
        if (i == i1) continue;
        if (i2 < 0 || gsm[i] > gsm[i2]) i2 = i;
    }
    float rs = fmaxf(gsm[i1] + gsm[i2], EPSF);
    float routed[4];
#pragma unroll
    for (int i = 0; i < 4; i++)
        routed[i] = (i == i1 || i == i2) ? gsm[i] / rs * 2.f : 0.f;
    float m1 = fmaxf(fmaxf(d[4], d[5]), fmaxf(d[6], d[7]));
    float es[4], ss = 0.f;
#pragma unroll
    for (int i = 0; i < 4; i++) { es[i] = expf(d[4 + i] - m1); ss += es[i]; }
    float shg[4];
#pragma unroll
    for (int i = 0; i < 4; i++) shg[i] = es[i] / ss * 4.f;
    float m2 = fmaxf(d[8], d[9]);
    float e8 = expf(d[8] - m2), e9 = expf(d[9] - m2);
    float w00 = e8 / (e8 + e9) * 2.f;
    float w01 = e9 / (e8 + e9) * 2.f;
    if (lane < NH) {
        float v = (lane < 4) ? w00 * shg[lane] : w01 * routed[lane - 4];
        g_gate[(size_t)t * NH + lane] = v;
    }
}

// ---------------- q postprocess ---------------------------------------------
__global__ void __launch_bounds__(256)
q_post(const float* __restrict__ temp, const float* __restrict__ qe) {
    int bn = blockIdx.x;
    int h = threadIdx.x >> 5, lane = threadIdx.x & 31;
    int n = bn & (NTOK - 1);
    size_t off = (size_t)bn * CDIM + h * HD + lane;
    float v = g_q[off];
    float nrm = sqrtf(warp_sum(v * v));
    float qn = v / fmaxf(nrm, EPSF);
    int y = n >> 6, x = n & 63;
    int ch = min(y + 1, 63) - max(y - 1, 0) + 1;
    int cw = min(x + 1, 63) - max(x - 1, 0) + 1;
    float sls = logf((float)(ch * cw + PLP));
    float sp = log1pf(expf(temp[h]));
    g_q [off] = qn;
    g_qs[off] = (qn + qe[h * HD + lane]) * sp * sls;
}

__global__ void __launch_bounds__(256) kv_post() {
    int bn = blockIdx.x;
    int h = threadIdx.x >> 5, lane = threadIdx.x & 31;
    size_t off = (size_t)bn * 2 * CDIM + h * HD + lane;
    float v = g_kv[off];
    float nrm = sqrtf(warp_sum(v * v));
    g_kv[off] = v / fmaxf(nrm, EPSF);
}

__global__ void __launch_bounds__(256) kvpool_post() {
    int bp = blockIdx.x;
    int h = threadIdx.x >> 5, lane = threadIdx.x & 31;
    size_t off = (size_t)bp * 2 * CDIM + h * HD + lane;
    float v = g_kvp[off];
    float nrm = sqrtf(warp_sum(v * v));
    g_kvp[off] = v / fmaxf(nrm, EPSF);
}

// ---------------- 8x8 avg pool + LayerNorm ----------------------------------
__global__ void __launch_bounds__(256)
pool_ln(const float* __restrict__ gw, const float* __restrict__ gb) {
    int bp = blockIdx.x;
    int b = bp >> 6, p = bp & 63;
    int py = p >> 3, px = p & 7;
    int c = threadIdx.x;
    const float* base = g_sr + (size_t)b * NTOK * CDIM;
    float s = 0.f;
    for (int iy = 0; iy < 8; iy++) {
        int y = py * 8 + iy;
        for (int ix = 0; ix < 8; ix++) {
            int n = y * RESHW + px * 8 + ix;
            s += base[(size_t)n * CDIM + c];
        }
    }
    float val = s * (1.0f / 64.0f);
    __shared__ float red[256];
    red[c] = val; __syncthreads();
    for (int st = 128; st > 0; st >>= 1) { if (c < st) red[c] += red[c + st]; __syncthreads(); }
    float mu = red[0] * (1.0f / 256.0f);
    __syncthreads();
    float dv = val - mu;
    red[c] = dv * dv; __syncthreads();
    for (int st = 128; st > 0; st >>= 1) { if (c < st) red[c] += red[c + st]; __syncthreads(); }
    float var = red[0] * (1.0f / 256.0f);
    g_pool[(size_t)bp * CDIM + c] = dv * rsqrtf(var + 1e-5f) * gw[c] + gb[c];
}

// ---------------- cpb MLP ----------------------------------------------------
__global__ void __launch_bounds__(128)
cpb_kernel(const float* __restrict__ tbl, const float* __restrict__ w1,
           const float* __restrict__ b1, const float* __restrict__ w2,
           const float* __restrict__ b2) {
    int row = blockIdx.x;
    int tid = threadIdx.x;
    float t0 = tbl[row * 2 + 0], t1 = tbl[row * 2 + 1];
    float acc[8] = {};
    for (int j = tid; j < 512; j += 128) {
        float hv = fmaxf(t0 * w1[2 * j] + t1 * w1[2 * j + 1] + b1[j], 0.f);
#pragma unroll
        for (int o = 0; o < 8; o++) acc[o] += hv * w2[o * 512 + j];
    }
#pragma unroll
    for (int o = 0; o < 8; o++) acc[o] = warp_sum(acc[o]);
    __shared__ float sh[4][8];
    int wp = tid >> 5, lane = tid & 31;
    if (lane == 0)
#pragma unroll
        for (int o = 0; o < 8; o++) sh[wp][o] = acc[o];
    __syncthreads();
    if (tid < 8)
        g_cpb[(size_t)row * 8 + tid] =
            sh[0][tid] + sh[1][tid] + sh[2][tid] + sh[3][tid] + b2[tid];
}

// ---------------- fused attention core --------------------------------------
__global__ void __launch_bounds__(256)
attn_kernel(const float* __restrict__ rpb, const float* __restrict__ lt,
            const float* __restrict__ lb, const int* __restrict__ rel_idx) {
    int blk = blockIdx.x;
    int ntile = blk & 511;
    int h = (blk >> 9) & 7;
    int b = blk >> 12;
    int w = threadIdx.x >> 5, lane = threadIdx.x & 31;
    __shared__ float kp[64][33];
    __shared__ float vp[64][33];
    __shared__ float logit[8][80];
    __shared__ float qsh[8][32];
    for (int i = threadIdx.x; i < 64 * 32; i += 256) {
        int p = i >> 5, d = i & 31;
        size_t base = (size_t)(b * PLP + p) * 2 * CDIM + h * HD + d;
        kp[p][d] = g_kvp[base];
        vp[p][d] = g_kvp[base + CDIM];
    }
    __syncthreads();
    int n = ntile * 8 + w;
    int y = n >> 6, x = n & 63;
    size_t qoff = (size_t)(b * NTOK + n) * CDIM + h * HD + lane;
    float qsv = g_qs[qoff];
    float qnv = g_q[qoff];
    qsh[w][lane] = qsv;
#pragma unroll
    for (int l = 0; l < 9; l++) {
        int yy = y + l / 3 - 1, xx = x + l % 3 - 1;
        float dot = 0.f;
        if ((unsigned)yy < 64u && (unsigned)xx < 64u) {
            int n2 = yy * RESHW + xx;
            dot = warp_sum(qsv * g_kv[(size_t)(b * NTOK + n2) * 2 * CDIM + h * HD + lane]);
        }
        if (lane == 0) logit[w][l] = dot + rpb[h * 9 + l];
    }
    __syncwarp();
    const int* ridx = rel_idx + (size_t)n * PLP;
#pragma unroll
    for (int rr = 0; rr < 2; rr++) {
        int p = lane + rr * 32;
        float dot = 0.f;
#pragma unroll
        for (int j = 0; j < 32; j++) dot += qsh[w][j] * kp[p][j];
        logit[w][9 + p] = dot + g_cpb[(size_t)ridx[p] * 8 + h];
    }
    __syncwarp();
    float v0 = logit[w][lane];
    float v1 = logit[w][lane + 32];
    float v2 = (lane < 9) ? logit[w][lane + 64] : -3.4e38f;
    float mx = warp_max(fmaxf(fmaxf(v0, v1), v2));
    float e0 = expf(v0 - mx), e1 = expf(v1 - mx);
    float e2 = (lane < 9) ? expf(v2 - mx) : 0.f;
    float inv = 1.0f / warp_sum(e0 + e1 + e2);
    logit[w][lane] = e0 * inv;
    logit[w][lane + 32] = e1 * inv;
    if (lane < 9) logit[w][lane + 64] = e2 * inv;
    __syncwarp();
#pragma unroll
    for (int l = 0; l < 9; l++) {
        float d2 = warp_sum(qnv * lt[h * (HD * 9) + lane * 9 + l]);
        if (lane == 0) logit[w][l] += d2 + lb[h * 9 + l];
    }
    __syncwarp();
    float outv = 0.f;
#pragma unroll
    for (int l = 0; l < 9; l++) {
        int yy = y + l / 3 - 1, xx = x + l % 3 - 1;
        if ((unsigned)yy < 64u && (unsigned)xx < 64u) {
            int n2 = yy * RESHW + xx;
            outv += logit[w][l] *
                    g_kv[(size_t)(b * NTOK + n2) * 2 * CDIM + CDIM + h * HD + lane];
        }
    }
#pragma unroll 8
    for (int p = 0; p < 64; p++) outv += logit[w][9 + p] * vp[p][lane];
    float gt = g_gate[(size_t)(b * NTOK + n) * NH + h];
    g_att[(size_t)(b * NTOK + n) * CDIM + h * HD + lane] = outv * gt;
}

// ---------------- launch ----------------------------------------------------
extern "C" void kernel_launch(void* const* d_in, const int* in_sizes, int n_in,
                              void* d_out, int out_size) {
    const float* x      = (const float*)d_in[0];
    const float* rct    = (const float*)d_in[1];
    const float* q_w    = (const float*)d_in[2];
    const float* q_b    = (const float*)d_in[3];
    const float* kv_w   = (const float*)d_in[4];
    const float* kv_b   = (const float*)d_in[5];
    const float* temp   = (const float*)d_in[6];
    const float* qe     = (const float*)d_in[7];
    const float* rpb    = (const float*)d_in[8];
    const float* lt     = (const float*)d_in[9];
    const float* lb     = (const float*)d_in[10];
    const float* cpb1_w = (const float*)d_in[11];
    const float* cpb1_b = (const float*)d_in[12];
    const float* cpb2_w = (const float*)d_in[13];
    const float* cpb2_b = (const float*)d_in[14];
    const float* sr_w   = (const float*)d_in[15];
    const float* sr_b   = (const float*)d_in[16];
    const float* norm_g = (const float*)d_in[17];
    const float* norm_b = (const float*)d_in[18];
    const float* wg_w   = (const float*)d_in[19];
    const float* wg0_w  = (const float*)d_in[20];
    const float* wg1_w  = (const float*)d_in[21];
    const float* proj_w = (const float*)d_in[22];
    const float* proj_b = (const float*)d_in[23];
    const int*   ridx   = (const int*)d_in[24];
    float* out = (float*)d_out;

    float *pq, *pkv, *psr, *patt, *ppool, *pkvp;
    cudaGetSymbolAddress((void**)&pq,    g_q);
    cudaGetSymbolAddress((void**)&pkv,   g_kv);
    cudaGetSymbolAddress((void**)&psr,   g_sr);
    cudaGetSymbolAddress((void**)&patt,  g_att);
    cudaGetSymbolAddress((void**)&ppool, g_pool);
    cudaGetSymbolAddress((void**)&pkvp,  g_kvp);

    const int M = BATCH * NTOK;                       // 16384
    dim3 gq(CDIM / 128, M / 128);                     // 2 x 128
    dim3 gkv(2 * CDIM / 128, M / 128);                // 4 x 128
    dim3 gkvp(2 * CDIM / 128, (BATCH * PLP) / 128);   // 4 x 2

    gemm_bf16x3<0><<<gq,  256>>>(x, q_w, q_b, pq, M, CDIM);
    gemm_bf16x3<0><<<gkv, 256>>>(x, kv_w, kv_b, pkv, M, 2 * CDIM);
    gemm_bf16x3<1><<<gq,  256>>>(x, sr_w, sr_b, psr, M, CDIM);
    gating_kernel<<<M / 8, 256>>>(x, wg_w, wg0_w, wg1_w);
    q_post<<<M, 256>>>(temp, qe);
    kv_post<<<M, 256>>>();
    pool_ln<<<BATCH * PLP, 256>>>(norm_g, norm_b);
    gemm_bf16x3<0><<<gkvp, 256>>>(ppool, kv_w, kv_b, pkvp, BATCH * PLP, 2 * CDIM);
    kvpool_post<<<BATCH * PLP, 256>>>();
    cpb_kernel<<<TBLN, 128>>>(rct, cpb1_w, cpb1_b, cpb2_w, cpb2_b);
    attn_kernel<<<BATCH * NH * (NTOK / 8), 256>>>(rpb, lt, lb, ridx);
    gemm_bf16x3<0><<<gq, 256>>>(patt, proj_w, proj_b, out, M, CDIM);
}

// round 4
// speedup vs baseline: 1.3472x; 1.0040x over previous
#include <cuda_runtime.h>
#include <cuda_bf16.h>
#include <math.h>
#include <stdint.h>

#define BATCH 4
#define NTOK  4096      // N = 64*64
#define CDIM  256
#define NH    8
#define HD    32
#define RESHW 64
#define PLP   64        // pooled length (8*8)
#define TBLN  4096
#define EPSF  1.1920929e-07f

// ---------------- scratch (device globals; no dynamic alloc) ----------------
__device__ float g_q   [BATCH*NTOK*CDIM];
__device__ float g_qs  [BATCH*NTOK*CDIM];
__device__ float g_kv  [BATCH*NTOK*2*CDIM];
__device__ float g_sr  [BATCH*NTOK*CDIM];
__device__ float g_gate[BATCH*NTOK*NH];
__device__ float g_kvp [BATCH*PLP*2*CDIM];
__device__ float g_cpb [TBLN*NH];
// bf16 hi/lo split operands for tensor-core GEMMs
__device__ __nv_bfloat16 g_xh [BATCH*NTOK*CDIM];
__device__ __nv_bfloat16 g_xl [BATCH*NTOK*CDIM];
__device__ __nv_bfloat16 g_wh [1280*CDIM];   // q(0) kv(256) sr(768) proj(1024)
__device__ __nv_bfloat16 g_wl [1280*CDIM];
__device__ __nv_bfloat16 g_ph [BATCH*PLP*CDIM];   // pooled+LN hi
__device__ __nv_bfloat16 g_pl [BATCH*PLP*CDIM];
__device__ __nv_bfloat16 g_ah [BATCH*NTOK*CDIM];  // attention out hi
__device__ __nv_bfloat16 g_al [BATCH*NTOK*CDIM];

__device__ __forceinline__ float warp_sum(float v) {
#pragma unroll
    for (int o = 16; o; o >>= 1) v += __shfl_xor_sync(0xffffffffu, v, o);
    return v;
}
__device__ __forceinline__ float warp_max(float v) {
#pragma unroll
    for (int o = 16; o; o >>= 1) v = fmaxf(v, __shfl_xor_sync(0xffffffffu, v, o));
    return v;
}

// ================= helpers ==================================================
__device__ __forceinline__ uint32_t smem_u32(const void* p) {
    uint32_t a;
    asm("{ .reg .u64 t; cvta.to.shared.u64 t, %1; cvt.u32.u64 %0, t; }"
        : "=r"(a) : "l"(p));
    return a;
}
__device__ __forceinline__ void ldsm_x4(uint32_t* r, uint32_t addr) {
    asm volatile("ldmatrix.sync.aligned.m8n8.x4.shared.b16 {%0,%1,%2,%3}, [%4];"
                 : "=r"(r[0]), "=r"(r[1]), "=r"(r[2]), "=r"(r[3]) : "r"(addr));
}
__device__ __forceinline__ void ldsm_x2(uint32_t* r, uint32_t addr) {
    asm volatile("ldmatrix.sync.aligned.m8n8.x2.shared.b16 {%0,%1}, [%2];"
                 : "=r"(r[0]), "=r"(r[1]) : "r"(addr));
}
__device__ __forceinline__ void mma_bf16(float* c, const uint32_t* a,
                                         const uint32_t* b) {
    asm volatile(
        "mma.sync.aligned.m16n8k16.row.col.f32.bf16.bf16.f32 "
        "{%0,%1,%2,%3}, {%4,%5,%6,%7}, {%8,%9}, {%0,%1,%2,%3};"
        : "+f"(c[0]), "+f"(c[1]), "+f"(c[2]), "+f"(c[3])
        : "r"(a[0]), "r"(a[1]), "r"(a[2]), "r"(a[3]), "r"(b[0]), "r"(b[1]));
}
__device__ __forceinline__ void cp16(uint32_t dst, const void* src) {
    asm volatile("cp.async.cg.shared.global [%0], [%1], 16;"
                 :: "r"(dst), "l"(src));
}
#define CP_COMMIT() asm volatile("cp.async.commit_group;" ::: "memory")
#define CP_WAIT0()  asm volatile("cp.async.wait_group 0;" ::: "memory")

// ---------------- f32 -> bf16 hi/lo split (vectorized) ----------------------
__global__ void __launch_bounds__(256)
convert_split(const float4* __restrict__ src, ushort4* __restrict__ hi,
              ushort4* __restrict__ lo, int n4) {
    int i = blockIdx.x * 256 + threadIdx.x;
    if (i >= n4) return;
    float4 v = src[i];
    __nv_bfloat16 h0 = __float2bfloat16(v.x), h1 = __float2bfloat16(v.y);
    __nv_bfloat16 h2 = __float2bfloat16(v.z), h3 = __float2bfloat16(v.w);
    __nv_bfloat16 l0 = __float2bfloat16(v.x - __bfloat162float(h0));
    __nv_bfloat16 l1 = __float2bfloat16(v.y - __bfloat162float(h1));
    __nv_bfloat16 l2 = __float2bfloat16(v.z - __bfloat162float(h2));
    __nv_bfloat16 l3 = __float2bfloat16(v.w - __bfloat162float(h3));
    ushort4 H, L;
    H.x = *(uint16_t*)&h0; H.y = *(uint16_t*)&h1;
    H.z = *(uint16_t*)&h2; H.w = *(uint16_t*)&h3;
    L.x = *(uint16_t*)&l0; L.y = *(uint16_t*)&l1;
    L.z = *(uint16_t*)&l2; L.w = *(uint16_t*)&l3;
    hi[i] = H; lo[i] = L;
}

// ================= double-buffered 3-term bf16 GEMM =========================
// C = A[*,256] @ W[*,256]^T (+bias, region epilogue). Tile 128x128, 8 warps.
// MODE 0: fused q/kv/sr outputs.  MODE 1: plain single output.
#define MATSZ (128 * 40)
#define GSMEM (2 * 4 * MATSZ * 2)   // 81920 B

template<int MODE>
__global__ void __launch_bounds__(256)
gemm_bf16(const __nv_bfloat16* __restrict__ Ah, const __nv_bfloat16* __restrict__ Al,
          const __nv_bfloat16* __restrict__ Wh, const __nv_bfloat16* __restrict__ Wl,
          float* __restrict__ C0, float* __restrict__ C1, float* __restrict__ C2,
          const float* __restrict__ b0, const float* __restrict__ b1,
          const float* __restrict__ b2, int ldc0) {
    extern __shared__ uint16_t sd[];
    const int bm = blockIdx.y * 128, bn = blockIdx.x * 128;
    const int tid = threadIdx.x, lane = tid & 31, wid = tid >> 5;
    const int wm = (wid & 3) * 32, wn = (wid >> 2) * 64;
    float acc[2][8][4] = {};

    const __nv_bfloat16* gsrc[4] = {
        Ah + (size_t)bm * 256, Al + (size_t)bm * 256,
        Wh + (size_t)bn * 256, Wl + (size_t)bn * 256};

    // prologue: load chunk 0 into stage 0
#pragma unroll
    for (int m = 0; m < 4; m++)
#pragma unroll
        for (int s = 0; s < 2; s++) {
            int seg = tid + s * 256;
            int row = seg >> 2, part = seg & 3;
            cp16(smem_u32(sd + m * MATSZ + row * 40 + part * 8),
                 gsrc[m] + (size_t)row * 256 + part * 8);
        }
    CP_COMMIT();

    for (int kc = 0; kc < 8; kc++) {
        const int stg = kc & 1;
        CP_WAIT0();
        __syncthreads();
        if (kc < 7) {
            const int nb = (stg ^ 1) * 4 * MATSZ;
            const int ko = (kc + 1) * 32;
#pragma unroll
            for (int m = 0; m < 4; m++)
#pragma unroll
                for (int s = 0; s < 2; s++) {
                    int seg = tid + s * 256;
                    int row = seg >> 2, part = seg & 3;
                    cp16(smem_u32(sd + nb + m * MATSZ + row * 40 + part * 8),
                         gsrc[m] + (size_t)row * 256 + ko + part * 8);
                }
            CP_COMMIT();
        }
        uint16_t* pAh = sd + (stg * 4 + 0) * MATSZ;
        uint16_t* pAl = sd + (stg * 4 + 1) * MATSZ;
        uint16_t* pBh = sd + (stg * 4 + 2) * MATSZ;
        uint16_t* pBl = sd + (stg * 4 + 3) * MATSZ;
#pragma unroll
        for (int ks = 0; ks < 2; ks++) {
            uint32_t ah[2][4], al[2][4];
            const int arow = lane & 15, acol = ks * 16 + (lane >> 4) * 8;
#pragma unroll
            for (int i = 0; i < 2; i++) {
                ldsm_x4(ah[i], smem_u32(pAh + (wm + i * 16 + arow) * 40 + acol));
                ldsm_x4(al[i], smem_u32(pAl + (wm + i * 16 + arow) * 40 + acol));
            }
            const int brow0 = wn + (lane & 7);
            const int bcol = ks * 16 + ((lane >> 3) & 1) * 8;
#pragma unroll
            for (int j = 0; j < 8; j++) {
                uint32_t bh[2], bl[2];
                ldsm_x2(bh, smem_u32(pBh + (brow0 + j * 8) * 40 + bcol));
                ldsm_x2(bl, smem_u32(pBl + (brow0 + j * 8) * 40 + bcol));
#pragma unroll
                for (int i = 0; i < 2; i++) {
                    mma_bf16(acc[i][j], ah[i], bh);
                    mma_bf16(acc[i][j], ah[i], bl);
                    mma_bf16(acc[i][j], al[i], bh);
                }
            }
        }
    }
    // epilogue
    float* C; const float* bias; int ldc, cb, act = 0;
    if (MODE == 0) {
        int r = bn >> 7;
        if (r < 2)      { C = C0; bias = b0; ldc = 256; cb = bn; }
        else if (r < 6) { C = C1; bias = b1; ldc = 512; cb = bn - 256; }
        else            { C = C2; bias = b2; ldc = 256; cb = bn - 768; act = 1; }
    } else {
        C = C0; bias = b0; ldc = ldc0; cb = bn;
    }
#pragma unroll
    for (int i = 0; i < 2; i++) {
        int r0 = bm + wm + i * 16 + (lane >> 2);
#pragma unroll
        for (int j = 0; j < 8; j++) {
            int col = cb + wn + j * 8 + (lane & 3) * 2;
            float bb0 = bias[col], bb1 = bias[col + 1];
            float v0 = acc[i][j][0] + bb0, v1 = acc[i][j][1] + bb1;
            float v2 = acc[i][j][2] + bb0, v3 = acc[i][j][3] + bb1;
            if (MODE == 0 && act) {
                v0 = 0.5f * v0 * (1.0f + erff(v0 * 0.70710678118654752f));
                v1 = 0.5f * v1 * (1.0f + erff(v1 * 0.70710678118654752f));
                v2 = 0.5f * v2 * (1.0f + erff(v2 * 0.70710678118654752f));
                v3 = 0.5f * v3 * (1.0f + erff(v3 * 0.70710678118654752f));
            }
            float2 o01; o01.x = v0; o01.y = v1;
            float2 o23; o23.x = v2; o23.y = v3;
            *(float2*)(C + (size_t)r0 * ldc + col) = o01;
            *(float2*)(C + (size_t)(r0 + 8) * ldc + col) = o23;
        }
    }
}

// ---------------- gating: one warp per token (float4 loads) ------------------
__global__ void __launch_bounds__(256)
gating_kernel(const float* __restrict__ x, const float* __restrict__ wg,
              const float* __restrict__ wg0, const float* __restrict__ wg1) {
    int t = blockIdx.x * 8 + (threadIdx.x >> 5);
    int lane = threadIdx.x & 31;
    const float* xt = x + (size_t)t * CDIM;
    float4 xa = *(const float4*)(xt + lane * 8);
    float4 xb = *(const float4*)(xt + lane * 8 + 4);
    float d[10];
#pragma unroll
    for (int i = 0; i < 10; i++) {
        const float* wr = (i < 4) ? wg + i * CDIM
                        : (i < 8) ? wg1 + (i - 4) * CDIM
                                  : wg0 + (i - 8) * CDIM;
        float4 wa = *(const float4*)(wr + lane * 8);
        float4 wb = *(const float4*)(wr + lane * 8 + 4);
        float s = xa.x * wa.x + xa.y * wa.y + xa.z * wa.z + xa.w * wa.w
                + xb.x * wb.x + xb.y * wb.y + xb.z * wb.z + xb.w * wb.w;
        d[i] = warp_sum(s);
    }
    float m0 = fmaxf(fmaxf(d[0], d[1]), fmaxf(d[2], d[3]));
    float e[4], se = 0.f;
#pragma unroll
    for (int i = 0; i < 4; i++) { e[i] = expf(d[i] - m0); se += e[i]; }
    float gsm[4];
#pragma unroll
    for (int i = 0; i < 4; i++) gsm[i] = e[i] / se;
    int i1 = 0;
#pragma unroll
    for (int i = 1; i < 4; i++) if (gsm[i] > gsm[i1]) i1 = i;
    int i2 = -1;
#pragma unroll
    for (int i = 0; i < 4; i++) {
        if (i == i1) continue;
        if (i2 < 0 || gsm[i] > gsm[i2]) i2 = i;
    }
    float rs = fmaxf(gsm[i1] + gsm[i2], EPSF);
    float routed[4];
#pragma unroll
    for (int i = 0; i < 4; i++)
        routed[i] = (i == i1 || i == i2) ? gsm[i] / rs * 2.f : 0.f;
    float m1 = fmaxf(fmaxf(d[4], d[5]), fmaxf(d[6], d[7]));
    float es[4], ss = 0.f;
#pragma unroll
    for (int i = 0; i < 4; i++) { es[i] = expf(d[4 + i] - m1); ss += es[i]; }
    float shg[4];
#pragma unroll
    for (int i = 0; i < 4; i++) shg[i] = es[i] / ss * 4.f;
    float m2 = fmaxf(d[8], d[9]);
    float e8 = expf(d[8] - m2), e9 = expf(d[9] - m2);
    float w00 = e8 / (e8 + e9) * 2.f;
    float w01 = e9 / (e8 + e9) * 2.f;
    if (lane < NH) {
        float v = (lane < 4) ? w00 * shg[lane] : w01 * routed[lane - 4];
        g_gate[(size_t)t * NH + lane] = v;
    }
}

// ---------------- q postprocess ---------------------------------------------
__global__ void __launch_bounds__(256)
q_post(const float* __restrict__ temp, const float* __restrict__ qe) {
    int bn = blockIdx.x;
    int h = threadIdx.x >> 5, lane = threadIdx.x & 31;
    int n = bn & (NTOK - 1);
    size_t off = (size_t)bn * CDIM + h * HD + lane;
    float v = g_q[off];
    float nrm = sqrtf(warp_sum(v * v));
    float qn = v / fmaxf(nrm, EPSF);
    int y = n >> 6, x = n & 63;
    int ch = min(y + 1, 63) - max(y - 1, 0) + 1;
    int cw = min(x + 1, 63) - max(x - 1, 0) + 1;
    float sls = logf((float)(ch * cw + PLP));
    float sp = log1pf(expf(temp[h]));
    g_q [off] = qn;
    g_qs[off] = (qn + qe[h * HD + lane]) * sp * sls;
}

__global__ void __launch_bounds__(256) kv_post() {
    int bn = blockIdx.x;
    int h = threadIdx.x >> 5, lane = threadIdx.x & 31;
    size_t off = (size_t)bn * 2 * CDIM + h * HD + lane;
    float v = g_kv[off];
    float nrm = sqrtf(warp_sum(v * v));
    g_kv[off] = v / fmaxf(nrm, EPSF);
}

__global__ void __launch_bounds__(256) kvpool_post() {
    int bp = blockIdx.x;
    int h = threadIdx.x >> 5, lane = threadIdx.x & 31;
    size_t off = (size_t)bp * 2 * CDIM + h * HD + lane;
    float v = g_kvp[off];
    float nrm = sqrtf(warp_sum(v * v));
    g_kvp[off] = v / fmaxf(nrm, EPSF);
}

// ---------------- 8x8 avg pool + LayerNorm (writes bf16 hi/lo) --------------
__global__ void __launch_bounds__(256)
pool_ln(const float* __restrict__ gw, const float* __restrict__ gb) {
    int bp = blockIdx.x;
    int b = bp >> 6, p = bp & 63;
    int py = p >> 3, px = p & 7;
    int c = threadIdx.x;
    const float* base = g_sr + (size_t)b * NTOK * CDIM;
    float s = 0.f;
    for (int iy = 0; iy < 8; iy++) {
        int y = py * 8 + iy;
        for (int ix = 0; ix < 8; ix++) {
            int n = y * RESHW + px * 8 + ix;
            s += base[(size_t)n * CDIM + c];
        }
    }
    float val = s * (1.0f / 64.0f);
    __shared__ float red[256];
    red[c] = val; __syncthreads();
    for (int st = 128; st > 0; st >>= 1) { if (c < st) red[c] += red[c + st]; __syncthreads(); }
    float mu = red[0] * (1.0f / 256.0f);
    __syncthreads();
    float dv = val - mu;
    red[c] = dv * dv; __syncthreads();
    for (int st = 128; st > 0; st >>= 1) { if (c < st) red[c] += red[c + st]; __syncthreads(); }
    float var = red[0] * (1.0f / 256.0f);
    float ov = dv * rsqrtf(var + 1e-5f) * gw[c] + gb[c];
    __nv_bfloat16 h = __float2bfloat16(ov);
    g_ph[(size_t)bp * CDIM + c] = h;
    g_pl[(size_t)bp * CDIM + c] = __float2bfloat16(ov - __bfloat162float(h));
}

// ---------------- cpb MLP ----------------------------------------------------
__global__ void __launch_bounds__(128)
cpb_kernel(const float* __restrict__ tbl, const float* __restrict__ w1,
           const float* __restrict__ b1, const float* __restrict__ w2,
           const float* __restrict__ b2) {
    int row = blockIdx.x;
    int tid = threadIdx.x;
    float t0 = tbl[row * 2 + 0], t1 = tbl[row * 2 + 1];
    float acc[8] = {};
    for (int j = tid; j < 512; j += 128) {
        float hv = fmaxf(t0 * w1[2 * j] + t1 * w1[2 * j + 1] + b1[j], 0.f);
#pragma unroll
        for (int o = 0; o < 8; o++) acc[o] += hv * w2[o * 512 + j];
    }
#pragma unroll
    for (int o = 0; o < 8; o++) acc[o] = warp_sum(acc[o]);
    __shared__ float sh[4][8];
    int wp = tid >> 5, lane = tid & 31;
    if (lane == 0)
#pragma unroll
        for (int o = 0; o < 8; o++) sh[wp][o] = acc[o];
    __syncthreads();
    if (tid < 8)
        g_cpb[(size_t)row * 8 + tid] =
            sh[0][tid] + sh[1][tid] + sh[2][tid] + sh[3][tid] + b2[tid];
}

// ---------------- fused attention: 32 tokens per block -----------------------
__global__ void __launch_bounds__(1024)
attn_kernel(const float* __restrict__ rpb, const float* __restrict__ lt,
            const float* __restrict__ lb, const int* __restrict__ rel_idx) {
    int blk = blockIdx.x;
    int ntile = blk & 127;
    int hh = (blk >> 7) & 7;
    int b = blk >> 10;
    int w = threadIdx.x >> 5, lane = threadIdx.x & 31;
    __shared__ float kp[64][33];
    __shared__ float vp[64][33];
    __shared__ float logit[32][80];
    __shared__ float qsh[32][32];
    for (int i = threadIdx.x; i < 64 * 32; i += 1024) {
        int p = i >> 5, d = i & 31;
        size_t base = (size_t)(b * PLP + p) * 2 * CDIM + hh * HD + d;
        kp[p][d] = g_kvp[base];
        vp[p][d] = g_kvp[base + CDIM];
    }
    __syncthreads();
    int n = ntile * 32 + w;
    int y = n >> 6, x = n & 63;
    size_t qoff = (size_t)(b * NTOK + n) * CDIM + hh * HD + lane;
    float qsv = g_qs[qoff];
    float qnv = g_q[qoff];
    qsh[w][lane] = qsv;
#pragma unroll
    for (int l = 0; l < 9; l++) {
        int yy = y + l / 3 - 1, xx = x + l % 3 - 1;
        float dot = 0.f;
        if ((unsigned)yy < 64u && (unsigned)xx < 64u) {
            int n2 = yy * RESHW + xx;
            dot = warp_sum(qsv * g_kv[(size_t)(b * NTOK + n2) * 2 * CDIM + hh * HD + lane]);
        }
        if (lane == 0) logit[w][l] = dot + rpb[hh * 9 + l];
    }
    __syncwarp();
    const int* ridx = rel_idx + (size_t)n * PLP;
#pragma unroll
    for (int rr = 0; rr < 2; rr++) {
        int p = lane + rr * 32;
        float dot = 0.f;
#pragma unroll
        for (int j = 0; j < 32; j++) dot += qsh[w][j] * kp[p][j];
        logit[w][9 + p] = dot + g_cpb[(size_t)ridx[p] * 8 + hh];
    }
    __syncwarp();
    float v0 = logit[w][lane];
    float v1 = logit[w][lane + 32];
    float v2 = (lane < 9) ? logit[w][lane + 64] : -3.4e38f;
    float mx = warp_max(fmaxf(fmaxf(v0, v1), v2));
    float e0 = expf(v0 - mx), e1 = expf(v1 - mx);
    float e2 = (lane < 9) ? expf(v2 - mx) : 0.f;
    float inv = 1.0f / warp_sum(e0 + e1 + e2);
    logit[w][lane] = e0 * inv;
    logit[w][lane + 32] = e1 * inv;
    if (lane < 9) logit[w][lane + 64] = e2 * inv;
    __syncwarp();
#pragma unroll
    for (int l = 0; l < 9; l++) {
        float d2 = warp_sum(qnv * lt[hh * (HD * 9) + lane * 9 + l]);
        if (lane == 0) logit[w][l] += d2 + lb[hh * 9 + l];
    }
    __syncwarp();
    float outv = 0.f;
#pragma unroll
    for (int l = 0; l < 9; l++) {
        int yy = y + l / 3 - 1, xx = x + l % 3 - 1;
        if ((unsigned)yy < 64u && (unsigned)xx < 64u) {
            int n2 = yy * RESHW + xx;
            outv += logit[w][l] *
                    g_kv[(size_t)(b * NTOK + n2) * 2 * CDIM + CDIM + hh * HD + lane];
        }
    }
#pragma unroll 8
    for (int p = 0; p < 64; p++) outv += logit[w][9 + p] * vp[p][lane];
    float gt = g_gate[(size_t)(b * NTOK + n) * NH + hh];
    float val = outv * gt;
    __nv_bfloat16 vh = __float2bfloat16(val);
    size_t oidx = (size_t)(b * NTOK + n) * CDIM + hh * HD + lane;
    g_ah[oidx] = vh;
    g_al[oidx] = __float2bfloat16(val - __bfloat162float(vh));
}

// ---------------- launch ----------------------------------------------------
extern "C" void kernel_launch(void* const* d_in, const int* in_sizes, int n_in,
                              void* d_out, int out_size) {
    const float* x      = (const float*)d_in[0];
    const float* rct    = (const float*)d_in[1];
    const float* q_w    = (const float*)d_in[2];
    const float* q_b    = (const float*)d_in[3];
    const float* kv_w   = (const float*)d_in[4];
    const float* kv_b   = (const float*)d_in[5];
    const float* temp   = (const float*)d_in[6];
    const float* qe     = (const float*)d_in[7];
    const float* rpb    = (const float*)d_in[8];
    const float* lt     = (const float*)d_in[9];
    const float* lb     = (const float*)d_in[10];
    const float* cpb1_w = (const float*)d_in[11];
    const float* cpb1_b = (const float*)d_in[12];
    const float* cpb2_w = (const float*)d_in[13];
    const float* cpb2_b = (const float*)d_in[14];
    const float* sr_w   = (const float*)d_in[15];
    const float* sr_b   = (const float*)d_in[16];
    const float* norm_g = (const float*)d_in[17];
    const float* norm_b = (const float*)d_in[18];
    const float* wg_w   = (const float*)d_in[19];
    const float* wg0_w  = (const float*)d_in[20];
    const float* wg1_w  = (const float*)d_in[21];
    const float* proj_w = (const float*)d_in[22];
    const float* proj_b = (const float*)d_in[23];
    const int*   ridx   = (const int*)d_in[24];
    float* out = (float*)d_out;

    float *pq, *pkv, *psr, *pkvp;
    __nv_bfloat16 *pxh, *pxl, *pwh, *pwl, *pph, *ppl, *pah, *pal;
    cudaGetSymbolAddress((void**)&pq,  g_q);
    cudaGetSymbolAddress((void**)&pkv, g_kv);
    cudaGetSymbolAddress((void**)&psr, g_sr);
    cudaGetSymbolAddress((void**)&pkvp, g_kvp);
    cudaGetSymbolAddress((void**)&pxh, g_xh);
    cudaGetSymbolAddress((void**)&pxl, g_xl);
    cudaGetSymbolAddress((void**)&pwh, g_wh);
    cudaGetSymbolAddress((void**)&pwl, g_wl);
    cudaGetSymbolAddress((void**)&pph, g_ph);
    cudaGetSymbolAddress((void**)&ppl, g_pl);
    cudaGetSymbolAddress((void**)&pah, g_ah);
    cudaGetSymbolAddress((void**)&pal, g_al);

    cudaFuncSetAttribute(gemm_bf16<0>,
                         cudaFuncAttributeMaxDynamicSharedMemorySize, GSMEM);
    cudaFuncSetAttribute(gemm_bf16<1>,
                         cudaFuncAttributeMaxDynamicSharedMemorySize, GSMEM);

    const int M = BATCH * NTOK;                       // 16384

    // split passes
    convert_split<<<M * CDIM / 4 / 256, 256>>>(
        (const float4*)x, (ushort4*)pxh, (ushort4*)pxl, M * CDIM / 4);
    convert_split<<<64, 256>>>((const float4*)q_w,
        (ushort4*)pwh, (ushort4*)pwl, 256 * 256 / 4);
    convert_split<<<128, 256>>>((const float4*)kv_w,
        (ushort4*)(pwh + 256 * 256), (ushort4*)(pwl + 256 * 256), 512 * 256 / 4);
    convert_split<<<64, 256>>>((const float4*)sr_w,
        (ushort4*)(pwh + 768 * 256), (ushort4*)(pwl + 768 * 256), 256 * 256 / 4);
    convert_split<<<64, 256>>>((const float4*)proj_w,
        (ushort4*)(pwh + 1024 * 256), (ushort4*)(pwl + 1024 * 256), 256 * 256 / 4);

    // fused q/kv/sr GEMM
    dim3 gf(8, M / 128);
    gemm_bf16<0><<<gf, 256, GSMEM>>>(pxh, pxl, pwh, pwl,
                                     pq, pkv, psr, q_b, kv_b, sr_b, 0);
    gating_kernel<<<M / 8, 256>>>(x, wg_w, wg0_w, wg1_w);
    q_post<<<M, 256>>>(temp, qe);
    kv_post<<<M, 256>>>();
    pool_ln<<<BATCH * PLP, 256>>>(norm_g, norm_b);
    dim3 gp(4, 2);
    gemm_bf16<1><<<gp, 256, GSMEM>>>(pph, ppl, pwh + 256 * 256, pwl + 256 * 256,
                                     pkvp, nullptr, nullptr, kv_b, nullptr,
                                     nullptr, 512);
    kvpool_post<<<BATCH * PLP, 256>>>();
    cpb_kernel<<<TBLN, 128>>>(rct, cpb1_w, cpb1_b, cpb2_w, cpb2_b);
    attn_kernel<<<BATCH * NH * (NTOK / 32), 1024>>>(rpb, lt, lb, ridx);
    dim3 gj(2, M / 128);
    gemm_bf16<1><<<gj, 256, GSMEM>>>(pah, pal, pwh + 1024 * 256, pwl + 1024 * 256,
                                     out, nullptr, nullptr, proj_b, nullptr,
                                     nullptr, 256);
}